// round 17
// baseline (speedup 1.0000x reference)
#include <cuda_runtime.h>
#include <math.h>

// Problem shape (fixed): x [T=4, B=32, C=256, H=32, W=32]
#define Tn 4
#define Bn 32
#define Cn 256
#define Pn 1024
#define NSL 2048            // slices = B * 64 pixel-groups (16 pixels, all 256 channels)
#define NBLK 148            // persistent grid = one CTA per SM

// Per-pixel sums: [sel][b][p], sel 0 = csum, 1 = ssq. 256 KB, L2-resident.
__device__ float g_comb[2 * Bn * Pn];

// ---------------------------------------------------------------------------
// Persistent reduce, 2-deep register pipeline.
// Slice = (b, pg): 16 pixels x 256 channels x 4 t. Thread: c = tid>>2,
// f4 = tid&3 (one float4 = 4 pixels). 4 x LDG.128 per thread per slice,
// issued TWO slices ahead (issue->consume distance = 2 iterations >> DRAM
// latency). Warp = 8 channels x 4 quads; 3 shuffle rounds reduce channels;
// pad-17 transposed combine (conflict-free), parity double-buffer, one
// barrier per slice.
// ---------------------------------------------------------------------------
__global__ void __launch_bounds__(1024, 1) reduce_kernel(const float* __restrict__ xf) {
    const float4* __restrict__ X = (const float4*)xf;
    const int tid = threadIdx.x;
    const int w   = tid >> 5;             // warp 0..31
    const int l   = tid & 31;
    const int c   = tid >> 2;             // channel 0..255
    const int f4  = tid & 3;              // pixel quad within the 16-pixel group

    __shared__ float scs[2][32][17];      // [parity][warp][16 scalars + pad]
    __shared__ float ssq[2][32][17];

    const size_t tstr = (size_t)Bn * Cn * 256;   // t-plane stride in float4

    const int sl0 = blockIdx.x;

    float4 rA[4], rB[4];

    // preload slice sl0 -> rA, slice sl0+NBLK -> rB
    {
        const int b = sl0 >> 6, pg = sl0 & 63;
        const size_t base = (size_t)b * Cn * 256 + (size_t)c * 256 + pg * 4 + f4;
#pragma unroll
        for (int t = 0; t < 4; ++t) rA[t] = __ldg(X + base + (size_t)t * tstr);
    }
    if (sl0 + NBLK < NSL) {
        const int s1 = sl0 + NBLK;
        const int b = s1 >> 6, pg = s1 & 63;
        const size_t base = (size_t)b * Cn * 256 + (size_t)c * 256 + pg * 4 + f4;
#pragma unroll
        for (int t = 0; t < 4; ++t) rB[t] = __ldg(X + base + (size_t)t * tstr);
    }

    int sl  = sl0;
    int par = 0;

    // body: consume buf (slice cur), prefetch cur+2*NBLK into buf, reduce+write
    auto body = [&](float4* buf, const int cur, const int p) {
        float4 m;
        m.x = (buf[0].x + buf[1].x + buf[2].x + buf[3].x) * 0.25f;
        m.y = (buf[0].y + buf[1].y + buf[2].y + buf[3].y) * 0.25f;
        m.z = (buf[0].z + buf[1].z + buf[2].z + buf[3].z) * 0.25f;
        m.w = (buf[0].w + buf[1].w + buf[2].w + buf[3].w) * 0.25f;

        float4 cs4 = m;
        float4 sq4 = make_float4(m.x * m.x, m.y * m.y, m.z * m.z, m.w * m.w);

        // prefetch slice cur + 2*NBLK into this buffer (2 iterations ahead)
        const int nxt2 = cur + 2 * NBLK;
        if (nxt2 < NSL) {
            const int b = nxt2 >> 6, pg = nxt2 & 63;
            const size_t base = (size_t)b * Cn * 256 + (size_t)c * 256 + pg * 4 + f4;
#pragma unroll
            for (int t = 0; t < 4; ++t) buf[t] = __ldg(X + base + (size_t)t * tstr);
        }

        // reduce over the 8 channels in this warp sharing quad f4
#pragma unroll
        for (int off = 4; off <= 16; off <<= 1) {
            cs4.x += __shfl_xor_sync(0xFFFFFFFFu, cs4.x, off);
            cs4.y += __shfl_xor_sync(0xFFFFFFFFu, cs4.y, off);
            cs4.z += __shfl_xor_sync(0xFFFFFFFFu, cs4.z, off);
            cs4.w += __shfl_xor_sync(0xFFFFFFFFu, cs4.w, off);
            sq4.x += __shfl_xor_sync(0xFFFFFFFFu, sq4.x, off);
            sq4.y += __shfl_xor_sync(0xFFFFFFFFu, sq4.y, off);
            sq4.z += __shfl_xor_sync(0xFFFFFFFFu, sq4.z, off);
            sq4.w += __shfl_xor_sync(0xFFFFFFFFu, sq4.w, off);
        }
        // lanes 0..3 hold the warp partial for quad l (pixels l*4..l*4+3)
        if (l < 4) {
            scs[p][w][l * 4 + 0] = cs4.x;
            scs[p][w][l * 4 + 1] = cs4.y;
            scs[p][w][l * 4 + 2] = cs4.z;
            scs[p][w][l * 4 + 3] = cs4.w;
            ssq[p][w][l * 4 + 0] = sq4.x;
            ssq[p][w][l * 4 + 1] = sq4.y;
            ssq[p][w][l * 4 + 2] = sq4.z;
            ssq[p][w][l * 4 + 3] = sq4.w;
        }
        __syncthreads();      // the ONLY barrier per slice (parity double-buffer)

        // transposed combine: warp j handles output scalar (sel = j>>4, idx = j&15).
        // read arr[p][l][idx]: bank = (17*l + idx) % 32, 17 coprime 32 -> conflict-free
        {
            const int sel = w >> 4, idx = w & 15;
            float v = sel ? ssq[p][l][idx] : scs[p][l][idx];
#pragma unroll
            for (int off = 16; off; off >>= 1)
                v += __shfl_xor_sync(0xFFFFFFFFu, v, off);
            if (l == 0) {
                const int b = cur >> 6, pg = cur & 63;
                g_comb[(size_t)sel * (Bn * Pn) + b * 1024 + pg * 16 + idx] = v;
            }
        }
    };

    for (;;) {
        body(rA, sl, par);
        sl += NBLK; if (sl >= NSL) break; par ^= 1;
        body(rB, sl, par);
        sl += NBLK; if (sl >= NSL) break; par ^= 1;
    }
}

// ---------------------------------------------------------------------------
// Final (R15): 256 threads per batch, 4 consecutive pixels per thread.
// ---------------------------------------------------------------------------
__global__ void __launch_bounds__(256) final_kernel(const int* __restrict__ mask,
                                                    float* __restrict__ out) {
    const int b    = blockIdx.x;
    const int tid  = threadIdx.x;          // 0..255; pixels [4*tid, 4*tid+3]
    const int h    = tid >> 3;             // row 0..31
    const int w4   = tid & 7;              // quad within row
    const int lane = tid & 31;
    const int wid  = tid >> 5;             // 0..7

    const float4 cs4 = __ldg((const float4*)g_comb + (size_t)b * 256 + tid);
    const float4 sq4 = __ldg((const float4*)g_comb + (size_t)(Bn + b) * 256 + tid);
    const int4  mr4  = __ldg((const int4*)mask + (size_t)b * 256 + tid);

    __shared__ float s_cs[34 * 34];
    for (int i = tid; i < 34 * 34; i += 256) s_cs[i] = 0.f;
    __syncthreads();
    {
        float* row = &s_cs[(h + 1) * 34 + (w4 * 4 + 1)];
        row[0] = cs4.x; row[1] = cs4.y; row[2] = cs4.z; row[3] = cs4.w;
    }
    __syncthreads();

    float colsum[6];
#pragma unroll
    for (int j = 0; j < 6; ++j) {
        const int cc = w4 * 4 + j;
        colsum[j] = s_cs[h * 34 + cc] + s_cs[(h + 1) * 34 + cc] + s_cs[(h + 2) * 34 + cc];
    }
    float box[4];
#pragma unroll
    for (int j = 0; j < 4; ++j) box[j] = colsum[j] + colsum[j + 1] + colsum[j + 2];

    const float csv[4] = {cs4.x, cs4.y, cs4.z, cs4.w};
    const float sqv[4] = {sq4.x, sq4.y, sq4.z, sq4.w};
    const int   mrv[4] = {mr4.x, mr4.y, mr4.z, mr4.w};
    float score[4];
#pragma unroll
    for (int j = 0; j < 4; ++j) {
        const float lm  = box[j] * (1.f / 9.f);
        const float nx  = sqrtf(sqv[j]);
        const float ny  = 16.f * fabsf(lm);   // sqrt(C)=16
        const float sim = (lm * csv[j]) / (fmaxf(nx, 1e-6f) * fmaxf(ny, 1e-6f));
        score[j] = mrv[j] ? -INFINITY : -sim;
    }

    __shared__ float red[8];
    __shared__ float bc[2];

    float m = fmaxf(fmaxf(score[0], score[1]), fmaxf(score[2], score[3]));
#pragma unroll
    for (int o = 16; o; o >>= 1) m = fmaxf(m, __shfl_xor_sync(0xFFFFFFFFu, m, o));
    if (lane == 0) red[wid] = m;
    __syncthreads();
    if (tid < 8) {
        float v = red[tid];
#pragma unroll
        for (int o = 4; o; o >>= 1) v = fmaxf(v, __shfl_xor_sync(0xFFu, v, o));
        if (tid == 0) bc[0] = v;
    }
    __syncthreads();
    const float gmax = bc[0];

    float e[4];
    float s = 0.f;
#pragma unroll
    for (int j = 0; j < 4; ++j) { e[j] = __expf(score[j] - gmax); s += e[j]; }
#pragma unroll
    for (int o = 16; o; o >>= 1) s += __shfl_xor_sync(0xFFFFFFFFu, s, o);
    if (lane == 0) red[wid] = s;
    __syncthreads();
    if (tid < 8) {
        float v = red[tid];
#pragma unroll
        for (int o = 4; o; o >>= 1) v += __shfl_xor_sync(0xFFu, v, o);
        if (tid == 0) bc[1] = v;
    }
    __syncthreads();

    const float inv = __frcp_rn(bc[1]);
    float4 o4 = make_float4(e[0] * inv, e[1] * inv, e[2] * inv, e[3] * inv);
    ((float4*)out)[(size_t)b * 256 + tid] = o4;
}

// ---------------------------------------------------------------------------
extern "C" void kernel_launch(void* const* d_in, const int* in_sizes, int n_in,
                              void* d_out, int out_size) {
    const float* x = (const float*)d_in[0];
    const int* mask = (const int*)d_in[1];
    float* out = (float*)d_out;

    reduce_kernel<<<NBLK, 1024>>>(x);
    final_kernel<<<Bn, 256>>>(mask, out);
}